// round 7
// baseline (speedup 1.0000x reference)
#include <cuda_runtime.h>

// ---------------------------------------------------------------------------
// Photonic Clements mesh, N=128. One warp per column; lane t owns rows
// 8t..8t+7 as 8 complex float2 registers v0..v7 (scalar FFMA — the f32x2
// path regressed on sm_100a and was reverted).
//
// ROUND 7 changes vs the 27.4us round-5 kernel:
//  1. D+M fusion: table stores (u,w) = (A*e^{i th}, B*e^{i th}) per layer/port;
//     each fused stage is one 3-deep FMA chain per output instead of two
//     dependent stages. Layer 254 (bare D, no trailing M) stored unfused.
//  2. Shfl hoisting: boundary pairs (v0,v1),(v6,v7) are advanced through both
//     fused stages FIRST, the 4 CROSS shuffles are issued, and the middle
//     pairs' math runs under the shfl latency.
// Output serialization identical to rounds 4-6 (mode on out_size).
// ---------------------------------------------------------------------------

#define NCOLS   128
#define NLAYERS 255
#define FULL    0xffffffffu

#define AM_  0.97467943448089633f    // sqrt(1-0.05)
#define PP_  0.71063352017759484f    // sqrt(0.5+0.005)
#define QQ_  0.70356236397351441f    // sqrt(0.5-0.005)
#define AMP_ (AM_*PP_)               // A (MMI)
#define AMQ_ (AM_*QQ_)               // B (MMI)
#define AX_  0.98994949366116653f    // sqrt(1-0.02)
#define XC_  (AX_*0.1f)                       // aX*sqrt(CT)
#define XS_  (AX_*0.99498743710661995f)       // aX*sqrt(1-CT), corner scalar

// fused table: layer k (<254), port j: (A*c, A*s, B*c, B*s); k=254: (c,s,0,0)
__device__ float4 g_uw[NLAYERS * NCOLS];

__global__ void phase_kernel(const float* __restrict__ theta_even) {
    int i = blockIdx.x * blockDim.x + threadIdx.x;
    if (i < NLAYERS * NCOLS) {
        float s, c;
        sincosf(theta_even[i], &s, &c);
        int k = i >> 7;   // /128
        float4 e;
        if (k < 254) e = make_float4(AMP_ * c, AMP_ * s, AMQ_ * c, AMQ_ * s);
        else         e = make_float4(c, s, 0.f, 0.f);
        g_uw[i] = e;
    }
}

// fused D+M stage:  a' = u*a + iB*b ;  b' = (i*w)*a + A*b
// q = (u.x, u.y, w.x, w.y)
#define FUSE(a, b, q) do { \
    float _ax = fmaf((q).x, (a).x, fmaf(-(q).y, (a).y, -AMQ_ * (b).y)); \
    float _ay = fmaf((q).y, (a).x, fmaf( (q).x, (a).y,  AMQ_ * (b).x)); \
    float _bx = fmaf(-(q).w, (a).x, fmaf(-(q).z, (a).y, AMP_ * (b).x)); \
    float _by = fmaf( (q).z, (a).x, fmaf(-(q).w, (a).y, AMP_ * (b).y)); \
    (a).x = _ax; (a).y = _ay; (b).x = _bx; (b).y = _by; } while (0)

// plain 2x2 mixer for CROSS interior: [a;b] <- [[A,iB],[iB,A]][a;b]
#define MIX(a, b, A, B) do { \
    float _ar = fmaf((A), (a).x, -(B) * (b).y); \
    float _ai = fmaf((A), (a).y,  (B) * (b).x); \
    float _br = fmaf((A), (b).x, -(B) * (a).y); \
    float _bi = fmaf((A), (b).y,  (B) * (a).x); \
    (a).x = _ar; (a).y = _ai; (b).x = _br; (b).y = _bi; } while (0)

// bare phase (layer 254): v *= (c + i s)
#define CMUL(v, c_, s_) do { \
    float _nx = fmaf((v).x, (c_), -(v).y * (s_)); \
    float _ny = fmaf((v).x, (s_),  (v).y * (c_)); \
    (v).x = _nx; (v).y = _ny; } while (0)

// One virtual iteration: FUSE(layer a), FUSE(layer b), CROSS — with the
// boundary pairs advanced first so the shuffles overlap the middle math.
#define ITER(S) do { \
    FUSE(v0, v1, (S)[0]); \
    FUSE(v6, v7, (S)[3]); \
    FUSE(v0, v1, (S)[4]); \
    FUSE(v6, v7, (S)[7]); \
    float _nb0x = __shfl_down_sync(FULL, v0.x, 1);   /* lane t+1's v0 = row 8t+8 */ \
    float _nb0y = __shfl_down_sync(FULL, v0.y, 1); \
    float _nb7x = __shfl_up_sync  (FULL, v7.x, 1);   /* lane t-1's v7 = row 8t-1 */ \
    float _nb7y = __shfl_up_sync  (FULL, v7.y, 1); \
    FUSE(v2, v3, (S)[1]); \
    FUSE(v4, v5, (S)[2]); \
    FUSE(v2, v3, (S)[5]); \
    FUSE(v4, v5, (S)[6]); \
    MIX(v1, v2, XC_, XS_); \
    MIX(v3, v4, XC_, XS_); \
    MIX(v5, v6, XC_, XS_); \
    float _n7x = fmaf(XC_, v7.x, -XS_ * _nb0y); \
    float _n7y = fmaf(XC_, v7.y,  XS_ * _nb0x); \
    float _n0x = fmaf(XC_, v0.x, -XS_ * _nb7y); \
    float _n0y = fmaf(XC_, v0.y,  XS_ * _nb7x); \
    v7.x = (t < 31) ? _n7x : XS_ * v7.x;   /* row 255 corner */ \
    v7.y = (t < 31) ? _n7y : XS_ * v7.y; \
    v0.x = (t > 0)  ? _n0x : XS_ * v0.x;   /* row 0 corner */ \
    v0.y = (t > 0)  ? _n0y : XS_ * v0.y; } while (0)

#define LD_SLOT(S, ka, kb) do { \
    (S)[0] = g_uw[(ka) * NCOLS + 4 * t + 0]; \
    (S)[1] = g_uw[(ka) * NCOLS + 4 * t + 1]; \
    (S)[2] = g_uw[(ka) * NCOLS + 4 * t + 2]; \
    (S)[3] = g_uw[(ka) * NCOLS + 4 * t + 3]; \
    (S)[4] = g_uw[(kb) * NCOLS + 4 * t + 0]; \
    (S)[5] = g_uw[(kb) * NCOLS + 4 * t + 1]; \
    (S)[6] = g_uw[(kb) * NCOLS + 4 * t + 2]; \
    (S)[7] = g_uw[(kb) * NCOLS + 4 * t + 3]; } while (0)

__global__ void __launch_bounds__(32, 1)
mesh_kernel(const float* __restrict__ theta_in,
            const float* __restrict__ theta_out,
            float* __restrict__ out,
            int mode)   // 1 = real-only (16384 floats), 2 = planar (32768 floats)
{
    const int c = blockIdx.x;    // column (input port)
    const int t = threadIdx.x;   // lane: rows 8t..8t+7

    float2 v0 = {0.f, 0.f}, v1 = {0.f, 0.f}, v2 = {0.f, 0.f}, v3 = {0.f, 0.f};
    float2 v4 = {0.f, 0.f}, v5 = {0.f, 0.f}, v6 = {0.f, 0.f}, v7 = {0.f, 0.f};

    // --- input: rows 2c, 2c+1 of column c of MMI_IN @ diag(e^{i th_in}) ---
    {
        float s, co;
        sincosf(theta_in[c], &s, &co);
        float2 ain = make_float2( AMP_ * co, AMP_ * s);   //  aM*p * e^{i th}
        float2 bin = make_float2(-AMQ_ * s,  AMQ_ * co);  // i*aM*q * e^{i th}
        int slot = 2 * c - 8 * t;
        if      (slot == 0) { v0 = ain; v1 = bin; }
        else if (slot == 2) { v2 = ain; v3 = bin; }
        else if (slot == 4) { v4 = ain; v5 = bin; }
        else if (slot == 6) { v6 = ain; v7 = bin; }
    }

    // --- first: FUSE(layer 0), CROSS ---
    {
        float4 p0 = g_uw[4 * t + 0], p1 = g_uw[4 * t + 1];
        float4 p2 = g_uw[4 * t + 2], p3 = g_uw[4 * t + 3];
        FUSE(v0, v1, p0);
        FUSE(v6, v7, p3);
        float nb0x = __shfl_down_sync(FULL, v0.x, 1);
        float nb0y = __shfl_down_sync(FULL, v0.y, 1);
        float nb7x = __shfl_up_sync  (FULL, v7.x, 1);
        float nb7y = __shfl_up_sync  (FULL, v7.y, 1);
        FUSE(v2, v3, p1);
        FUSE(v4, v5, p2);
        MIX(v1, v2, XC_, XS_);
        MIX(v3, v4, XC_, XS_);
        MIX(v5, v6, XC_, XS_);
        float n7x = fmaf(XC_, v7.x, -XS_ * nb0y);
        float n7y = fmaf(XC_, v7.y,  XS_ * nb0x);
        float n0x = fmaf(XC_, v0.x, -XS_ * nb7y);
        float n0y = fmaf(XC_, v0.y,  XS_ * nb7x);
        v7.x = (t < 31) ? n7x : XS_ * v7.x;
        v7.y = (t < 31) ? n7y : XS_ * v7.y;
        v0.x = (t > 0)  ? n0x : XS_ * v0.x;
        v0.y = (t > 0)  ? n0y : XS_ * v0.y;
    }

    // iteration j (0..125) consumes layers 2j+1, 2j+2; virtual j=126 -> (253,254)
    float4 s0[8], s1[8];
    LD_SLOT(s0, 1, 2);
    LD_SLOT(s1, 3, 4);

#pragma unroll 1
    for (int j = 0; j < 126; j += 2) {
        {
            int jn = (j + 2 <= 126) ? (j + 2) : 126;
            float4 nx[8];
            LD_SLOT(nx, 2 * jn + 1, 2 * jn + 2);
            ITER(s0);
#pragma unroll
            for (int m = 0; m < 8; m++) s0[m] = nx[m];
        }
        {
            int jn = (j + 3 <= 126) ? (j + 3) : 126;
            float4 nx[8];
            LD_SLOT(nx, 2 * jn + 1, 2 * jn + 2);
            ITER(s1);
#pragma unroll
            for (int m = 0; m < 8; m++) s1[m] = nx[m];
        }
    }

    // --- tail: FUSE(253) then bare D254 (s0 holds layers 253,254) ---
    FUSE(v0, v1, s0[0]);
    FUSE(v2, v3, s0[1]);
    FUSE(v4, v5, s0[2]);
    FUSE(v6, v7, s0[3]);
    CMUL(v0, s0[4].x, s0[4].y);
    CMUL(v2, s0[5].x, s0[5].y);
    CMUL(v4, s0[6].x, s0[6].y);
    CMUL(v6, s0[7].x, s0[7].y);

    // --- output rows jj = 4t..4t+3: MMI_OUT pair reduce, then e^{i th_out} ---
#define OUTP(va, vb, jj) do { \
        float _ox = fmaf(AMP_, (va).x, -AMQ_ * (vb).y); \
        float _oy = fmaf(AMP_, (va).y,  AMQ_ * (vb).x); \
        float _so, _co; sincosf(theta_out[jj], &_so, &_co); \
        float _re = _ox * _co - _oy * _so; \
        float _im = _ox * _so + _oy * _co; \
        if (mode == 1) { out[(jj) * NCOLS + c] = _re; } \
        else { out[(jj) * NCOLS + c] = _re; \
               out[NCOLS * NCOLS + (jj) * NCOLS + c] = _im; } } while (0)

    OUTP(v0, v1, 4 * t);
    OUTP(v2, v3, 4 * t + 1);
    OUTP(v4, v5, 4 * t + 2);
    OUTP(v6, v7, 4 * t + 3);
#undef OUTP
}

extern "C" void kernel_launch(void* const* d_in, const int* in_sizes, int n_in,
                              void* d_out, int out_size) {
    // Inputs identified by SIZE (theta_even = unique 32640-elem array;
    // theta_in precedes theta_out).
    const float* th_ev  = nullptr;
    const float* small_[2] = {nullptr, nullptr};
    int ns = 0;
    for (int i = 0; i < n_in && i < 3; i++) {
        if (in_sizes[i] > 1000) th_ev = (const float*)d_in[i];
        else if (ns < 2)        small_[ns++] = (const float*)d_in[i];
    }
    const float* th_in  = small_[0];
    const float* th_out = small_[1];

    int mode = (out_size == NCOLS * NCOLS) ? 1 : 2;  // 16384 -> real-only, else planar

    phase_kernel<<<(NLAYERS * NCOLS + 255) / 256, 256>>>(th_ev);
    mesh_kernel<<<NCOLS, 32>>>(th_in, th_out, (float*)d_out, mode);
}